// round 15
// baseline (speedup 1.0000x reference)
#include <cuda_runtime.h>
#include <cuda_fp16.h>
#include <math.h>

#define S_LEN 2048
#define D_DIM 1024
#define NHEAD 16
#define HD    64
#define BATCH 2
#define BHSD  (BATCH * NHEAD * S_LEN * HD)

// Scratch: fp16 x/W/QKV/attn-out, packed mask bits
__device__ __half   g_xh[BATCH * S_LEN * D_DIM];
__device__ __half   g_Wh[4 * D_DIM * D_DIM];       // Wq,Wk,Wv,Wo stacked
__device__ unsigned g_Mp[BATCH * S_LEN * (S_LEN / 32)];
__device__ __half   g_QKV[3 * BHSD];
__device__ __half   g_attnh[BATCH * S_LEN * D_DIM];

// D(16x8) += A(16x16) * B(16x8), fp16 inputs, fp32 accum
__device__ __forceinline__ void mma16(float4& d, const unsigned* a, const unsigned* b) {
    asm volatile(
        "mma.sync.aligned.m16n8k16.row.col.f32.f16.f16.f32 "
        "{%0,%1,%2,%3}, {%4,%5,%6,%7}, {%8,%9}, {%0,%1,%2,%3};\n"
        : "+f"(d.x), "+f"(d.y), "+f"(d.z), "+f"(d.w)
        : "r"(a[0]), "r"(a[1]), "r"(a[2]), "r"(a[3]), "r"(b[0]), "r"(b[1]));
}

__device__ __forceinline__ void ldsm4(unsigned* r, unsigned addr) {
    asm volatile("ldmatrix.sync.aligned.m8n8.x4.shared.b16 {%0,%1,%2,%3}, [%4];\n"
        : "=r"(r[0]), "=r"(r[1]), "=r"(r[2]), "=r"(r[3]) : "r"(addr));
}
__device__ __forceinline__ void ldsm4t(unsigned* r, unsigned addr) {
    asm volatile("ldmatrix.sync.aligned.m8n8.x4.trans.shared.b16 {%0,%1,%2,%3}, [%4];\n"
        : "=r"(r[0]), "=r"(r[1]), "=r"(r[2]), "=r"(r[3]) : "r"(addr));
}

__device__ __forceinline__ void cp16(unsigned dst, const void* src) {
    asm volatile("cp.async.cg.shared.global [%0], [%1], 16;\n" :: "r"(dst), "l"(src));
}
#define CP_COMMIT() asm volatile("cp.async.commit_group;\n" ::)
#define CP_WAIT(N)  asm volatile("cp.async.wait_group %0;\n" :: "n"(N))

__device__ __forceinline__ unsigned h2u(float a, float b) {
    __half2 h = __floats2half2_rn(a, b);
    return *(unsigned*)&h;
}
__device__ __forceinline__ unsigned prmt(unsigned a, unsigned b, unsigned sel) {
    unsigned d;
    asm("prmt.b32 %0, %1, %2, %3;" : "=r"(d) : "r"(a), "r"(b), "r"(sel));
    return d;
}

// ---------------------------------------------------------------------------
// merged fp32 -> fp16 conversion: x (first 1048576 float4) then 4 weights
// ---------------------------------------------------------------------------
__global__ void cvt_all_kernel(const float* __restrict__ x,
                               const float* __restrict__ a, const float* __restrict__ b,
                               const float* __restrict__ c, const float* __restrict__ d,
                               __half* __restrict__ xh, __half* __restrict__ wh) {
    const int i = blockIdx.x * blockDim.x + threadIdx.x;
    const float* src;
    __half* dst;
    int j;
    if (i < 1048576) { src = x; dst = xh; j = i; }
    else {
        const int k = i - 1048576;
        const int which = k >> 18;
        j = k & 262143;
        src = (which == 0) ? a : (which == 1) ? b : (which == 2) ? c : d;
        dst = wh + (size_t)which * D_DIM * D_DIM;
    }
    float4 v = ((const float4*)src)[j];
    __half2 p[2];
    p[0] = __floats2half2_rn(v.x, v.y);
    p[1] = __floats2half2_rn(v.z, v.w);
    *(uint2*)(dst + (size_t)j * 4) = *(const uint2*)p;
}

__global__ void pack_mask_kernel(const int* __restrict__ M, unsigned* __restrict__ P) {
    const int wg   = (blockIdx.x * blockDim.x + threadIdx.x) >> 5;
    const int lane = threadIdx.x & 31;
    const size_t base = (size_t)wg * 256;
    #pragma unroll
    for (int j = 0; j < 8; j++) {
        int v = M[base + j * 32 + lane];
        unsigned bm = __ballot_sync(0xffffffffu, v != 0);
        if (lane == 0) P[wg * 8 + j] = bm;
    }
}

// ---------------------------------------------------------------------------
// fp16 GEMM: C[M,N] = A[M,K=1024] @ W[N,K]^T. Tile 128x128, K-chunk 64 halves,
// 16 iters, 3-stage cp.async, ldmatrix fragments. 256 thr = 8 warps (4Mx2N).
// ---------------------------------------------------------------------------
__global__ __launch_bounds__(256, 2) void gemm_f16(
    const __half* __restrict__ A, const __half* __restrict__ W,
    const float* __restrict__ bias, void* __restrict__ Cv, int head_major)
{
    extern __shared__ __half smh[];
    __half* sA = smh;                    // [3][128][72]
    __half* sB = smh + 3 * 128 * 72;     // [3][128][72]
    const unsigned sAa = (unsigned)__cvta_generic_to_shared(sA);
    const unsigned sBa = (unsigned)__cvta_generic_to_shared(sB);

    const int tid = threadIdx.x;
    const int warp = tid >> 5, lane = tid & 31;
    const int wm = warp >> 1, wn = warp & 1;
    const int r = lane >> 2;
    const int g = lane >> 3, lr8 = lane & 7;
    const int m0 = blockIdx.y * 128, n0 = blockIdx.x * 128;

    unsigned aoff[2], boff[4];
    #pragma unroll
    for (int mi = 0; mi < 2; mi++)
        aoff[mi] = ((wm * 32 + mi * 16 + lr8 + (g & 1) * 8) * 72 + (g >> 1) * 8) * 2;
    #pragma unroll
    for (int p = 0; p < 4; p++)
        boff[p] = ((wn * 64 + p * 16 + (g >> 1) * 8 + lr8) * 72 + (g & 1) * 8) * 2;

    auto issue = [&](int it, int buf) {
        const int kc = it * 64;
        #pragma unroll
        for (int j = 0; j < 4; j++) {
            const int id = tid + j * 256;
            const int row = id >> 3, c8 = (id & 7) * 8;
            cp16(sAa + (unsigned)((buf * 128 + row) * 72 + c8) * 2,
                 A + (size_t)(m0 + row) * 1024 + kc + c8);
            cp16(sBa + (unsigned)((buf * 128 + row) * 72 + c8) * 2,
                 W + (size_t)(n0 + row) * 1024 + kc + c8);
        }
        CP_COMMIT();
    };

    float4 acc[2][8];
    #pragma unroll
    for (int mi = 0; mi < 2; mi++)
        #pragma unroll
        for (int ni = 0; ni < 8; ni++) acc[mi][ni] = make_float4(0.f, 0.f, 0.f, 0.f);

    issue(0, 0);
    issue(1, 1);

    for (int it = 0; it < 16; ++it) {
        const int buf = it % 3;
        CP_WAIT(1);
        __syncthreads();
        if (it + 2 < 16) issue(it + 2, (it + 2) % 3);

        const unsigned bA = sAa + (unsigned)(buf * 128 * 72) * 2;
        const unsigned bB = sBa + (unsigned)(buf * 128 * 72) * 2;
        #pragma unroll
        for (int kk = 0; kk < 4; kk++) {
            unsigned af[2][4], bf[4][4];
            ldsm4(af[0], bA + aoff[0] + kk * 32);
            ldsm4(af[1], bA + aoff[1] + kk * 32);
            #pragma unroll
            for (int p = 0; p < 4; p++) ldsm4(bf[p], bB + boff[p] + kk * 32);
            #pragma unroll
            for (int mi = 0; mi < 2; mi++)
                #pragma unroll
                for (int ni = 0; ni < 8; ni++)
                    mma16(acc[mi][ni], af[mi], &bf[ni >> 1][(ni & 1) * 2]);
        }
    }

    const int c2 = (lane & 3) * 2;
    #pragma unroll
    for (int mi = 0; mi < 2; mi++) {
        #pragma unroll
        for (int ni = 0; ni < 8; ni++) {
            const int row = m0 + wm * 32 + mi * 16 + r;
            const int col = n0 + wn * 64 + ni * 8 + c2;
            if (!head_major) {
                float* C = (float*)Cv;
                const float bx = bias[col], by = bias[col + 1];
                *(float2*)(C + (size_t)row * 1024 + col) =
                    make_float2(acc[mi][ni].x + bx, acc[mi][ni].y + by);
                *(float2*)(C + (size_t)(row + 8) * 1024 + col) =
                    make_float2(acc[mi][ni].z + bx, acc[mi][ni].w + by);
            } else {
                __half* C = (__half*)Cv;
                const int qkv = col >> 10, rem = col & 1023;
                const int bb = row >> 11, s = row & 2047;
                const int hh = rem >> 6, cc = rem & 63;
                __half* base = C + ((size_t)qkv * (BATCH * NHEAD) + bb * NHEAD + hh) *
                                   (size_t)(S_LEN * HD) + cc;
                *(__half2*)(base + (size_t)s * 64) =
                    __floats2half2_rn(acc[mi][ni].x, acc[mi][ni].y);
                *(__half2*)(base + (size_t)(s + 8) * 64) =
                    __floats2half2_rn(acc[mi][ni].z, acc[mi][ni].w);
            }
        }
    }
}

// ---------------------------------------------------------------------------
// Flash attention: Q pre-scaled, unconditional exp2, PRMT bitwise mask, row
// sums via ones-mma (after PV), P in registers. Key tiles of 128 (2 x 64-key
// halves per barrier). 256 thr, 128 q rows.
// ---------------------------------------------------------------------------
#define SC2 0.18033688011112042f   // 0.125 * log2(e)

__global__ __launch_bounds__(256, 2) void attn_f16(
    const __half* __restrict__ Qg, const __half* __restrict__ Kg,
    const __half* __restrict__ Vg, const unsigned* __restrict__ Mp,
    __half* __restrict__ Og)
{
    extern __shared__ __half smh[];
    __half* sK = smh;                     // [2][128][72]
    __half* sV = smh + 2 * 128 * 72;      // [2][128][72]
    __half* sQ = smh + 4 * 128 * 72;      // [128][72]  (Q staging only)
    const unsigned sKa = (unsigned)__cvta_generic_to_shared(sK);
    const unsigned sVa = (unsigned)__cvta_generic_to_shared(sV);
    const unsigned sQa = (unsigned)__cvta_generic_to_shared(sQ);

    const int tid = threadIdx.x, w = tid >> 5, lane = tid & 31;
    const int r = lane >> 2, cq = lane & 3, c2 = cq * 2;
    const int g = lane >> 3, lr8 = lane & 7;
    const int bh = blockIdx.y, b = bh >> 4, h = bh & 15;
    const int q0 = blockIdx.x * 128;
    const int rowb = w * 16;

    const __half* Qh = Qg + (size_t)bh * S_LEN * HD;
    const __half* Kh = Kg + (size_t)bh * S_LEN * HD;
    const __half* Vh = Vg + (size_t)bh * S_LEN * HD;
    const unsigned* Mr = Mp + ((size_t)b * S_LEN + q0 + rowb + r) * 64;

    const unsigned qoff = ((rowb + lr8 + (g & 1) * 8) * 72 + (g >> 1) * 8) * 2;  // Q A-frag
    unsigned koff[4];
    #pragma unroll
    for (int p = 0; p < 4; p++)
        koff[p] = ((p * 16 + (g >> 1) * 8 + lr8) * 72 + (g & 1) * 8) * 2;        // K B frag
    const unsigned voff = (((g & 1) * 8 + lr8) * 72 + (g >> 1) * 8) * 2;          // V B frag (trans)

    // 128-key tile load: K and V, 128 rows x 128B each
    auto issue_tile = [&](int t, int buf) {
        const __half* kg = Kh + (size_t)t * 128 * 64;
        const __half* vg = Vh + (size_t)t * 128 * 64;
        #pragma unroll
        for (int j = 0; j < 4; j++) {
            const int id = tid + j * 256;
            const int row = id >> 3, c8 = (id & 7) * 8;
            cp16(sKa + (unsigned)((buf * 128 + row) * 72 + c8) * 2, kg + row * 64 + c8);
            cp16(sVa + (unsigned)((buf * 128 + row) * 72 + c8) * 2, vg + row * 64 + c8);
        }
        CP_COMMIT();
    };

    issue_tile(0, 0);

    // Stage Q scaled by SC2
    const __half2 sc2h = __floats2half2_rn(SC2, SC2);
    for (int i = tid; i < 1024; i += 256) {
        const int row = i >> 3, c8 = (i & 7) * 8;
        uint4 v = *(const uint4*)(Qh + (size_t)(q0 + row) * 64 + c8);
        __half2* hp = (__half2*)&v;
        hp[0] = __hmul2(hp[0], sc2h); hp[1] = __hmul2(hp[1], sc2h);
        hp[2] = __hmul2(hp[2], sc2h); hp[3] = __hmul2(hp[3], sc2h);
        *(uint4*)&sQ[row * 72 + c8] = v;
    }
    __syncthreads();
    unsigned aq[4][4];
    #pragma unroll
    for (int kk = 0; kk < 4; kk++) ldsm4(aq[kk], sQa + qoff + kk * 32);

    const unsigned ONES2[2] = {0x3C003C00u, 0x3C003C00u};  // fp16 1.0 x4
    const unsigned SEL[4] = {0xCC88u, 0xDD99u, 0xEEAAu, 0xFFBBu};

    float4 acco[8];
    float4 accl = make_float4(0.f, 0.f, 0.f, 0.f);   // row sums via ones-mma
    #pragma unroll
    for (int ni = 0; ni < 8; ni++) acco[ni] = make_float4(0.f, 0.f, 0.f, 0.f);

    for (int t = 0; t < 16; t++) {          // 128-key tiles
        const int buf = t & 1;

        // prefetch mask words early (4 words per row = 128 keys)
        const uint4 w0 = *(const uint4*)(Mr + 4 * t);
        const uint4 w1 = *(const uint4*)(Mr + 512 + 4 * t);

        CP_WAIT(0);
        __syncthreads();
        if (t < 15) issue_tile(t + 1, buf ^ 1);

        #pragma unroll
        for (int hf = 0; hf < 2; hf++) {    // two 64-key halves, regs reused
            const unsigned K0 = sKa + (unsigned)((buf * 128 + hf * 64) * 72) * 2;
            const unsigned V0 = sVa + (unsigned)((buf * 128 + hf * 64) * 72) * 2;
            const unsigned mwa0 = hf ? w0.z : w0.x;   // keys [0,32) of half
            const unsigned mwa1 = hf ? w0.w : w0.y;   // keys [32,64)
            const unsigned mwb0 = hf ? w1.z : w1.x;
            const unsigned mwb1 = hf ? w1.w : w1.y;

            // S = Q K^T, K-frags double-buffered in registers
            float4 accs[8];
            #pragma unroll
            for (int ni = 0; ni < 8; ni++) accs[ni] = make_float4(0.f, 0.f, 0.f, 0.f);
            {
                unsigned bf[2][4][4];
                #pragma unroll
                for (int p = 0; p < 4; p++) ldsm4(bf[0][p], K0 + koff[p]);
                #pragma unroll
                for (int kk = 0; kk < 4; kk++) {
                    const int cur = kk & 1;
                    if (kk < 3) {
                        #pragma unroll
                        for (int p = 0; p < 4; p++)
                            ldsm4(bf[cur ^ 1][p], K0 + koff[p] + (kk + 1) * 32);
                    }
                    #pragma unroll
                    for (int ni = 0; ni < 8; ni++)
                        mma16(accs[ni], aq[kk], &bf[cur][ni >> 1][(ni & 1) * 2]);
                }
            }

            // PRMT sign-replicate masks: bits sh -> byte MSBs, 1 prmt per word
            const unsigned ua0 = mwa0 << (7 - c2), ua1 = mwa0 << (6 - c2);
            const unsigned ub0 = mwa1 << (7 - c2), ub1 = mwa1 << (6 - c2);
            const unsigned uc0 = mwb0 << (7 - c2), uc1 = mwb0 << (6 - c2);
            const unsigned ud0 = mwb1 << (7 - c2), ud1 = mwb1 << (6 - c2);

            unsigned ap[4][4];
            #pragma unroll
            for (int ni = 0; ni < 8; ni++) {
                unsigned pa = h2u(exp2f(accs[ni].x), exp2f(accs[ni].y));   // row r
                unsigned pb = h2u(exp2f(accs[ni].z), exp2f(accs[ni].w));   // row r+8
                const unsigned s = SEL[ni & 3];
                const unsigned ma = (ni < 4) ? prmt(ua0, ua1, s) : prmt(ub0, ub1, s);
                const unsigned mb = (ni < 4) ? prmt(uc0, uc1, s) : prmt(ud0, ud1, s);
                ap[ni >> 1][(ni & 1) * 2 + 0] = pa & ma;
                ap[ni >> 1][(ni & 1) * 2 + 1] = pb & mb;
            }

            // O += P V  (V frags double-buffered in registers)
            {
                unsigned vf[2][4][4];
                #pragma unroll
                for (int vi = 0; vi < 4; vi++) ldsm4t(vf[0][vi], V0 + voff + vi * 32);
                #pragma unroll
                for (int kk = 0; kk < 4; kk++) {
                    const int cur = kk & 1;
                    if (kk < 3) {
                        #pragma unroll
                        for (int vi = 0; vi < 4; vi++)
                            ldsm4t(vf[cur ^ 1][vi], V0 + voff + (kk + 1) * 16 * 144 + vi * 32);
                    }
                    #pragma unroll
                    for (int ni = 0; ni < 8; ni++)
                        mma16(acco[ni], ap[kk], &vf[cur][ni >> 1][(ni & 1) * 2]);
                }
            }

            // row sums via ones-mma (off the exp->PV critical path)
            #pragma unroll
            for (int kk = 0; kk < 4; kk++) mma16(accl, ap[kk], ONES2);
        }
    }

    // accl.x = full row-r sum, accl.z = row r+8 sum
    const float inv0 = 1.f / accl.x, inv1 = 1.f / accl.z;
    const int row0 = q0 + rowb + r;
    __half* Ob = Og + (size_t)b * S_LEN * D_DIM + (size_t)h * HD;
    #pragma unroll
    for (int ni = 0; ni < 8; ni++) {
        const int col = ni * 8 + c2;
        *(__half2*)(Ob + (size_t)row0 * D_DIM + col) =
            __floats2half2_rn(acco[ni].x * inv0, acco[ni].y * inv0);
        *(__half2*)(Ob + (size_t)(row0 + 8) * D_DIM + col) =
            __floats2half2_rn(acco[ni].z * inv1, acco[ni].w * inv1);
    }
}

// ---------------------------------------------------------------------------
extern "C" void kernel_launch(void* const* d_in, const int* in_sizes, int n_in,
                              void* d_out, int out_size)
{
    const float* x  = (const float*)d_in[0];
    const int*   M  = (const int*)d_in[1];
    const float* Wq = (const float*)d_in[2];
    const float* Wk = (const float*)d_in[3];
    const float* Wv = (const float*)d_in[4];
    const float* Wo = (const float*)d_in[5];
    const float* bo = (const float*)d_in[6];
    float* out = (float*)d_out;

    __half *xh, *Wh, *Qp, *Ah;
    unsigned* Mp;
    cudaGetSymbolAddress((void**)&xh, g_xh);
    cudaGetSymbolAddress((void**)&Wh, g_Wh);
    cudaGetSymbolAddress((void**)&Mp, g_Mp);
    cudaGetSymbolAddress((void**)&Qp, g_QKV);
    cudaGetSymbolAddress((void**)&Ah, g_attnh);

    // one-time infra (created on the uncaptured correctness call, reused in
    // the captured graph; deterministic topology every call)
    static cudaStream_t s_side = nullptr;
    static cudaEvent_t  e_fork = nullptr, e_join = nullptr;
    if (!s_side) {
        cudaStreamCreateWithFlags(&s_side, cudaStreamNonBlocking);
        cudaEventCreateWithFlags(&e_fork, cudaEventDisableTiming);
        cudaEventCreateWithFlags(&e_join, cudaEventDisableTiming);
    }

    // main stream: cvt -> QKV gemm ; side stream: mask pack (joined pre-attn)
    cudaEventRecord(e_fork, 0);
    cudaStreamWaitEvent(s_side, e_fork, 0);
    pack_mask_kernel<<<(BATCH * S_LEN * S_LEN / 8) / 256, 256, 0, s_side>>>(M, Mp);
    cudaEventRecord(e_join, s_side);

    cvt_all_kernel<<<2097152 / 256, 256>>>(x, Wq, Wk, Wv, Wo, xh, Wh);

    const int gemm_smem = 3 * 2 * 128 * 72 * 2;            // 110592
    const int attn_smem = 5 * 128 * 72 * 2;                // 92160
    cudaFuncSetAttribute(gemm_f16, cudaFuncAttributeMaxDynamicSharedMemorySize, gemm_smem);
    cudaFuncSetAttribute(attn_f16, cudaFuncAttributeMaxDynamicSharedMemorySize, attn_smem);

    // merged QKV GEMM: N = 3072 (overlaps with pack_mask on side stream)
    gemm_f16<<<dim3(3 * D_DIM / 128, (BATCH * S_LEN) / 128), 256, gemm_smem>>>(
        xh, Wh, nullptr, Qp, 1);

    cudaStreamWaitEvent(0, e_join, 0);    // mask bits ready before attn

    attn_f16<<<dim3(S_LEN / 128, BATCH * NHEAD), 256, attn_smem>>>(
        Qp, Qp + BHSD, Qp + 2 * BHSD, Mp, Ah);

    gemm_f16<<<dim3(D_DIM / 128, (BATCH * S_LEN) / 128), 256, gemm_smem>>>(
        Ah, Wh + 3 * D_DIM * D_DIM, bo, out, 0);
}

// round 16
// speedup vs baseline: 1.5183x; 1.5183x over previous
#include <cuda_runtime.h>
#include <cuda_fp16.h>
#include <math.h>

#define S_LEN 2048
#define D_DIM 1024
#define NHEAD 16
#define HD    64
#define BATCH 2
#define BHSD  (BATCH * NHEAD * S_LEN * HD)

// Scratch: fp16 x/W/QKV/attn-out, packed mask bits
__device__ __half   g_xh[BATCH * S_LEN * D_DIM];
__device__ __half   g_Wh[4 * D_DIM * D_DIM];       // Wq,Wk,Wv,Wo stacked
__device__ unsigned g_Mp[BATCH * S_LEN * (S_LEN / 32)];
__device__ __half   g_QKV[3 * BHSD];
__device__ __half   g_attnh[BATCH * S_LEN * D_DIM];

// D(16x8) += A(16x16) * B(16x8), fp16 inputs, fp32 accum
__device__ __forceinline__ void mma16(float4& d, const unsigned* a, const unsigned* b) {
    asm volatile(
        "mma.sync.aligned.m16n8k16.row.col.f32.f16.f16.f32 "
        "{%0,%1,%2,%3}, {%4,%5,%6,%7}, {%8,%9}, {%0,%1,%2,%3};\n"
        : "+f"(d.x), "+f"(d.y), "+f"(d.z), "+f"(d.w)
        : "r"(a[0]), "r"(a[1]), "r"(a[2]), "r"(a[3]), "r"(b[0]), "r"(b[1]));
}

__device__ __forceinline__ void ldsm4(unsigned* r, unsigned addr) {
    asm volatile("ldmatrix.sync.aligned.m8n8.x4.shared.b16 {%0,%1,%2,%3}, [%4];\n"
        : "=r"(r[0]), "=r"(r[1]), "=r"(r[2]), "=r"(r[3]) : "r"(addr));
}
__device__ __forceinline__ void ldsm4t(unsigned* r, unsigned addr) {
    asm volatile("ldmatrix.sync.aligned.m8n8.x4.trans.shared.b16 {%0,%1,%2,%3}, [%4];\n"
        : "=r"(r[0]), "=r"(r[1]), "=r"(r[2]), "=r"(r[3]) : "r"(addr));
}

__device__ __forceinline__ void cp16(unsigned dst, const void* src) {
    asm volatile("cp.async.cg.shared.global [%0], [%1], 16;\n" :: "r"(dst), "l"(src));
}
#define CP_COMMIT() asm volatile("cp.async.commit_group;\n" ::)
#define CP_WAIT(N)  asm volatile("cp.async.wait_group %0;\n" :: "n"(N))

__device__ __forceinline__ unsigned h2u(float a, float b) {
    __half2 h = __floats2half2_rn(a, b);
    return *(unsigned*)&h;
}
__device__ __forceinline__ unsigned prmt(unsigned a, unsigned b, unsigned sel) {
    unsigned d;
    asm("prmt.b32 %0, %1, %2, %3;" : "=r"(d) : "r"(a), "r"(b), "r"(sel));
    return d;
}

// ---------------------------------------------------------------------------
// Merged prep: blocks [0,8192) convert x + 4 weights to fp16;
// blocks [8192,12288) ballot-pack the mask to bits. One launch, one stream.
// ---------------------------------------------------------------------------
__global__ void prep_kernel(const float* __restrict__ x,
                            const float* __restrict__ a, const float* __restrict__ b,
                            const float* __restrict__ c, const float* __restrict__ d,
                            __half* __restrict__ xh, __half* __restrict__ wh,
                            const int* __restrict__ M, unsigned* __restrict__ P) {
    if (blockIdx.x < 8192) {
        const int i = blockIdx.x * 256 + threadIdx.x;
        const float* src;
        __half* dst;
        int j;
        if (i < 1048576) { src = x; dst = xh; j = i; }
        else {
            const int k = i - 1048576;
            const int which = k >> 18;
            j = k & 262143;
            src = (which == 0) ? a : (which == 1) ? b : (which == 2) ? c : d;
            dst = wh + (size_t)which * D_DIM * D_DIM;
        }
        float4 v = ((const float4*)src)[j];
        __half2 p[2];
        p[0] = __floats2half2_rn(v.x, v.y);
        p[1] = __floats2half2_rn(v.z, v.w);
        *(uint2*)(dst + (size_t)j * 4) = *(const uint2*)p;
    } else {
        const int wg   = ((blockIdx.x - 8192) * 256 + threadIdx.x) >> 5;
        const int lane = threadIdx.x & 31;
        const size_t base = (size_t)wg * 256;
        #pragma unroll
        for (int j = 0; j < 8; j++) {
            int v = M[base + j * 32 + lane];
            unsigned bm = __ballot_sync(0xffffffffu, v != 0);
            if (lane == 0) P[wg * 8 + j] = bm;
        }
    }
}

// ---------------------------------------------------------------------------
// fp16 GEMM: C[M,N] = A[M,K=1024] @ W[N,K]^T. Tile 128x128, K-chunk 64 halves,
// 16 iters, 3-stage cp.async, ldmatrix fragments. 256 thr = 8 warps (4Mx2N).
// ---------------------------------------------------------------------------
__global__ __launch_bounds__(256, 2) void gemm_f16(
    const __half* __restrict__ A, const __half* __restrict__ W,
    const float* __restrict__ bias, void* __restrict__ Cv, int head_major)
{
    extern __shared__ __half smh[];
    __half* sA = smh;                    // [3][128][72]
    __half* sB = smh + 3 * 128 * 72;     // [3][128][72]
    const unsigned sAa = (unsigned)__cvta_generic_to_shared(sA);
    const unsigned sBa = (unsigned)__cvta_generic_to_shared(sB);

    const int tid = threadIdx.x;
    const int warp = tid >> 5, lane = tid & 31;
    const int wm = warp >> 1, wn = warp & 1;
    const int r = lane >> 2;
    const int g = lane >> 3, lr8 = lane & 7;
    const int m0 = blockIdx.y * 128, n0 = blockIdx.x * 128;

    unsigned aoff[2], boff[4];
    #pragma unroll
    for (int mi = 0; mi < 2; mi++)
        aoff[mi] = ((wm * 32 + mi * 16 + lr8 + (g & 1) * 8) * 72 + (g >> 1) * 8) * 2;
    #pragma unroll
    for (int p = 0; p < 4; p++)
        boff[p] = ((wn * 64 + p * 16 + (g >> 1) * 8 + lr8) * 72 + (g & 1) * 8) * 2;

    auto issue = [&](int it, int buf) {
        const int kc = it * 64;
        #pragma unroll
        for (int j = 0; j < 4; j++) {
            const int id = tid + j * 256;
            const int row = id >> 3, c8 = (id & 7) * 8;
            cp16(sAa + (unsigned)((buf * 128 + row) * 72 + c8) * 2,
                 A + (size_t)(m0 + row) * 1024 + kc + c8);
            cp16(sBa + (unsigned)((buf * 128 + row) * 72 + c8) * 2,
                 W + (size_t)(n0 + row) * 1024 + kc + c8);
        }
        CP_COMMIT();
    };

    float4 acc[2][8];
    #pragma unroll
    for (int mi = 0; mi < 2; mi++)
        #pragma unroll
        for (int ni = 0; ni < 8; ni++) acc[mi][ni] = make_float4(0.f, 0.f, 0.f, 0.f);

    issue(0, 0);
    issue(1, 1);

    for (int it = 0; it < 16; ++it) {
        const int buf = it % 3;
        CP_WAIT(1);
        __syncthreads();
        if (it + 2 < 16) issue(it + 2, (it + 2) % 3);

        const unsigned bA = sAa + (unsigned)(buf * 128 * 72) * 2;
        const unsigned bB = sBa + (unsigned)(buf * 128 * 72) * 2;
        #pragma unroll
        for (int kk = 0; kk < 4; kk++) {
            unsigned af[2][4], bf[4][4];
            ldsm4(af[0], bA + aoff[0] + kk * 32);
            ldsm4(af[1], bA + aoff[1] + kk * 32);
            #pragma unroll
            for (int p = 0; p < 4; p++) ldsm4(bf[p], bB + boff[p] + kk * 32);
            #pragma unroll
            for (int mi = 0; mi < 2; mi++)
                #pragma unroll
                for (int ni = 0; ni < 8; ni++)
                    mma16(acc[mi][ni], af[mi], &bf[ni >> 1][(ni & 1) * 2]);
        }
    }

    const int c2 = (lane & 3) * 2;
    #pragma unroll
    for (int mi = 0; mi < 2; mi++) {
        #pragma unroll
        for (int ni = 0; ni < 8; ni++) {
            const int row = m0 + wm * 32 + mi * 16 + r;
            const int col = n0 + wn * 64 + ni * 8 + c2;
            if (!head_major) {
                float* C = (float*)Cv;
                const float bx = bias[col], by = bias[col + 1];
                *(float2*)(C + (size_t)row * 1024 + col) =
                    make_float2(acc[mi][ni].x + bx, acc[mi][ni].y + by);
                *(float2*)(C + (size_t)(row + 8) * 1024 + col) =
                    make_float2(acc[mi][ni].z + bx, acc[mi][ni].w + by);
            } else {
                __half* C = (__half*)Cv;
                const int qkv = col >> 10, rem = col & 1023;
                const int bb = row >> 11, s = row & 2047;
                const int hh = rem >> 6, cc = rem & 63;
                __half* base = C + ((size_t)qkv * (BATCH * NHEAD) + bb * NHEAD + hh) *
                                   (size_t)(S_LEN * HD) + cc;
                *(__half2*)(base + (size_t)s * 64) =
                    __floats2half2_rn(acc[mi][ni].x, acc[mi][ni].y);
                *(__half2*)(base + (size_t)(s + 8) * 64) =
                    __floats2half2_rn(acc[mi][ni].z, acc[mi][ni].w);
            }
        }
    }
}

// ---------------------------------------------------------------------------
// Flash attention: Q pre-scaled, unconditional exp2, PRMT bitwise mask, row
// sums via ones-mma (before PV, as in the 254us config), P in registers.
// Key tiles of 128 (2 x 64-key halves per barrier). 256 thr, 128 q rows.
// ---------------------------------------------------------------------------
#define SC2 0.18033688011112042f   // 0.125 * log2(e)

__global__ __launch_bounds__(256, 2) void attn_f16(
    const __half* __restrict__ Qg, const __half* __restrict__ Kg,
    const __half* __restrict__ Vg, const unsigned* __restrict__ Mp,
    __half* __restrict__ Og)
{
    extern __shared__ __half smh[];
    __half* sK = smh;                     // [2][128][72]
    __half* sV = smh + 2 * 128 * 72;      // [2][128][72]
    __half* sQ = smh + 4 * 128 * 72;      // [128][72]  (Q staging only)
    const unsigned sKa = (unsigned)__cvta_generic_to_shared(sK);
    const unsigned sVa = (unsigned)__cvta_generic_to_shared(sV);
    const unsigned sQa = (unsigned)__cvta_generic_to_shared(sQ);

    const int tid = threadIdx.x, w = tid >> 5, lane = tid & 31;
    const int r = lane >> 2, cq = lane & 3, c2 = cq * 2;
    const int g = lane >> 3, lr8 = lane & 7;
    const int bh = blockIdx.y, b = bh >> 4, h = bh & 15;
    const int q0 = blockIdx.x * 128;
    const int rowb = w * 16;

    const __half* Qh = Qg + (size_t)bh * S_LEN * HD;
    const __half* Kh = Kg + (size_t)bh * S_LEN * HD;
    const __half* Vh = Vg + (size_t)bh * S_LEN * HD;
    const unsigned* Mr = Mp + ((size_t)b * S_LEN + q0 + rowb + r) * 64;

    const unsigned qoff = ((rowb + lr8 + (g & 1) * 8) * 72 + (g >> 1) * 8) * 2;  // Q A-frag
    unsigned koff[4];
    #pragma unroll
    for (int p = 0; p < 4; p++)
        koff[p] = ((p * 16 + (g >> 1) * 8 + lr8) * 72 + (g & 1) * 8) * 2;        // K B frag
    const unsigned voff = (((g & 1) * 8 + lr8) * 72 + (g >> 1) * 8) * 2;          // V B frag (trans)

    // 128-key tile load: K and V, 128 rows x 128B each
    auto issue_tile = [&](int t, int buf) {
        const __half* kg = Kh + (size_t)t * 128 * 64;
        const __half* vg = Vh + (size_t)t * 128 * 64;
        #pragma unroll
        for (int j = 0; j < 4; j++) {
            const int id = tid + j * 256;
            const int row = id >> 3, c8 = (id & 7) * 8;
            cp16(sKa + (unsigned)((buf * 128 + row) * 72 + c8) * 2, kg + row * 64 + c8);
            cp16(sVa + (unsigned)((buf * 128 + row) * 72 + c8) * 2, vg + row * 64 + c8);
        }
        CP_COMMIT();
    };

    issue_tile(0, 0);

    // Stage Q scaled by SC2
    const __half2 sc2h = __floats2half2_rn(SC2, SC2);
    for (int i = tid; i < 1024; i += 256) {
        const int row = i >> 3, c8 = (i & 7) * 8;
        uint4 v = *(const uint4*)(Qh + (size_t)(q0 + row) * 64 + c8);
        __half2* hp = (__half2*)&v;
        hp[0] = __hmul2(hp[0], sc2h); hp[1] = __hmul2(hp[1], sc2h);
        hp[2] = __hmul2(hp[2], sc2h); hp[3] = __hmul2(hp[3], sc2h);
        *(uint4*)&sQ[row * 72 + c8] = v;
    }
    __syncthreads();
    unsigned aq[4][4];
    #pragma unroll
    for (int kk = 0; kk < 4; kk++) ldsm4(aq[kk], sQa + qoff + kk * 32);

    const unsigned ONES2[2] = {0x3C003C00u, 0x3C003C00u};  // fp16 1.0 x4
    const unsigned SEL[4] = {0xCC88u, 0xDD99u, 0xEEAAu, 0xFFBBu};

    float4 acco[8];
    float4 accl = make_float4(0.f, 0.f, 0.f, 0.f);   // row sums via ones-mma
    #pragma unroll
    for (int ni = 0; ni < 8; ni++) acco[ni] = make_float4(0.f, 0.f, 0.f, 0.f);

    for (int t = 0; t < 16; t++) {          // 128-key tiles
        const int buf = t & 1;

        // prefetch mask words early (4 words per row = 128 keys)
        const uint4 w0 = *(const uint4*)(Mr + 4 * t);
        const uint4 w1 = *(const uint4*)(Mr + 512 + 4 * t);

        CP_WAIT(0);
        __syncthreads();
        if (t < 15) issue_tile(t + 1, buf ^ 1);

        #pragma unroll
        for (int hf = 0; hf < 2; hf++) {    // two 64-key halves, regs reused
            const unsigned K0 = sKa + (unsigned)((buf * 128 + hf * 64) * 72) * 2;
            const unsigned V0 = sVa + (unsigned)((buf * 128 + hf * 64) * 72) * 2;
            const unsigned mwa0 = hf ? w0.z : w0.x;   // keys [0,32) of half
            const unsigned mwa1 = hf ? w0.w : w0.y;   // keys [32,64)
            const unsigned mwb0 = hf ? w1.z : w1.x;
            const unsigned mwb1 = hf ? w1.w : w1.y;

            // S = Q K^T, K-frags double-buffered in registers
            float4 accs[8];
            #pragma unroll
            for (int ni = 0; ni < 8; ni++) accs[ni] = make_float4(0.f, 0.f, 0.f, 0.f);
            {
                unsigned bf[2][4][4];
                #pragma unroll
                for (int p = 0; p < 4; p++) ldsm4(bf[0][p], K0 + koff[p]);
                #pragma unroll
                for (int kk = 0; kk < 4; kk++) {
                    const int cur = kk & 1;
                    if (kk < 3) {
                        #pragma unroll
                        for (int p = 0; p < 4; p++)
                            ldsm4(bf[cur ^ 1][p], K0 + koff[p] + (kk + 1) * 32);
                    }
                    #pragma unroll
                    for (int ni = 0; ni < 8; ni++)
                        mma16(accs[ni], aq[kk], &bf[cur][ni >> 1][(ni & 1) * 2]);
                }
            }

            // PRMT sign-replicate masks: bits sh -> byte MSBs, 1 prmt per word
            const unsigned ua0 = mwa0 << (7 - c2), ua1 = mwa0 << (6 - c2);
            const unsigned ub0 = mwa1 << (7 - c2), ub1 = mwa1 << (6 - c2);
            const unsigned uc0 = mwb0 << (7 - c2), uc1 = mwb0 << (6 - c2);
            const unsigned ud0 = mwb1 << (7 - c2), ud1 = mwb1 << (6 - c2);

            unsigned ap[4][4];
            #pragma unroll
            for (int ni = 0; ni < 8; ni++) {
                unsigned pa = h2u(exp2f(accs[ni].x), exp2f(accs[ni].y));   // row r
                unsigned pb = h2u(exp2f(accs[ni].z), exp2f(accs[ni].w));   // row r+8
                const unsigned s = SEL[ni & 3];
                const unsigned ma = (ni < 4) ? prmt(ua0, ua1, s) : prmt(ub0, ub1, s);
                const unsigned mb = (ni < 4) ? prmt(uc0, uc1, s) : prmt(ud0, ud1, s);
                ap[ni >> 1][(ni & 1) * 2 + 0] = pa & ma;
                ap[ni >> 1][(ni & 1) * 2 + 1] = pb & mb;
            }

            // row sums via ones-mma
            #pragma unroll
            for (int kk = 0; kk < 4; kk++) mma16(accl, ap[kk], ONES2);

            // O += P V  (V frags double-buffered in registers)
            {
                unsigned vf[2][4][4];
                #pragma unroll
                for (int vi = 0; vi < 4; vi++) ldsm4t(vf[0][vi], V0 + voff + vi * 32);
                #pragma unroll
                for (int kk = 0; kk < 4; kk++) {
                    const int cur = kk & 1;
                    if (kk < 3) {
                        #pragma unroll
                        for (int vi = 0; vi < 4; vi++)
                            ldsm4t(vf[cur ^ 1][vi], V0 + voff + (kk + 1) * 16 * 144 + vi * 32);
                    }
                    #pragma unroll
                    for (int ni = 0; ni < 8; ni++)
                        mma16(acco[ni], ap[kk], &vf[cur][ni >> 1][(ni & 1) * 2]);
                }
            }
        }
    }

    // accl.x = full row-r sum, accl.z = row r+8 sum
    const float inv0 = 1.f / accl.x, inv1 = 1.f / accl.z;
    const int row0 = q0 + rowb + r;
    __half* Ob = Og + (size_t)b * S_LEN * D_DIM + (size_t)h * HD;
    #pragma unroll
    for (int ni = 0; ni < 8; ni++) {
        const int col = ni * 8 + c2;
        *(__half2*)(Ob + (size_t)row0 * D_DIM + col) =
            __floats2half2_rn(acco[ni].x * inv0, acco[ni].y * inv0);
        *(__half2*)(Ob + (size_t)(row0 + 8) * D_DIM + col) =
            __floats2half2_rn(acco[ni].z * inv1, acco[ni].w * inv1);
    }
}

// ---------------------------------------------------------------------------
extern "C" void kernel_launch(void* const* d_in, const int* in_sizes, int n_in,
                              void* d_out, int out_size)
{
    const float* x  = (const float*)d_in[0];
    const int*   M  = (const int*)d_in[1];
    const float* Wq = (const float*)d_in[2];
    const float* Wk = (const float*)d_in[3];
    const float* Wv = (const float*)d_in[4];
    const float* Wo = (const float*)d_in[5];
    const float* bo = (const float*)d_in[6];
    float* out = (float*)d_out;

    __half *xh, *Wh, *Qp, *Ah;
    unsigned* Mp;
    cudaGetSymbolAddress((void**)&xh, g_xh);
    cudaGetSymbolAddress((void**)&Wh, g_Wh);
    cudaGetSymbolAddress((void**)&Mp, g_Mp);
    cudaGetSymbolAddress((void**)&Qp, g_QKV);
    cudaGetSymbolAddress((void**)&Ah, g_attnh);

    // merged prep: cvt (8192 blocks) + mask pack (4096 blocks), single stream
    prep_kernel<<<12288, 256>>>(x, Wq, Wk, Wv, Wo, xh, Wh, M, Mp);

    const int gemm_smem = 3 * 2 * 128 * 72 * 2;            // 110592
    const int attn_smem = 5 * 128 * 72 * 2;                // 92160
    cudaFuncSetAttribute(gemm_f16, cudaFuncAttributeMaxDynamicSharedMemorySize, gemm_smem);
    cudaFuncSetAttribute(attn_f16, cudaFuncAttributeMaxDynamicSharedMemorySize, attn_smem);

    // merged QKV GEMM: N = 3072
    gemm_f16<<<dim3(3 * D_DIM / 128, (BATCH * S_LEN) / 128), 256, gemm_smem>>>(
        xh, Wh, nullptr, Qp, 1);

    attn_f16<<<dim3(S_LEN / 128, BATCH * NHEAD), 256, attn_smem>>>(
        Qp, Qp + BHSD, Qp + 2 * BHSD, Mp, Ah);

    gemm_f16<<<dim3(D_DIM / 128, (BATCH * S_LEN) / 128), 256, gemm_smem>>>(
        Ah, Wh + 3 * D_DIM * D_DIM, bo, out, 0);
}